// round 2
// baseline (speedup 1.0000x reference)
#include <cuda_runtime.h>

// VQ-VAE quantization: z_e [65536, 256] f32, codebook [1024, 256] f32.
// Must bit-replicate reference semantics:
//   z_sq  = serial sum of rounded squares (mul then add, no FMA)
//   cross = serial ascending-k single-accumulator FMA (Eigen/cublas mainloop order)
//   dist  = fadd(fsub(z_sq, 2*cross), e_sq)   (rounds at ulp(~256) = 3e-5!)
//   argmin with lowest-index tie-break (jnp.argmin first occurrence)

#define NROWS   65536
#define DDIM    256
#define KCODES  1024
#define BM      128     // rows per block
#define BKC     128     // codes per chunk
#define DCH     32      // d-dim inner chunk
#define SSTR    132     // smem row stride (floats)
#define NBLOCKS (NROWS / BM)   // 512

__device__ float g_esq[KCODES];
__device__ float g_zsq[NROWS];
__device__ float g_partial[NBLOCKS];

// ||e_k||^2 : serial mul-then-add, ascending d (no FMA contraction)
__global__ void esq_kernel(const float* __restrict__ cb) {
    int k = blockIdx.x * blockDim.x + threadIdx.x;
    if (k >= KCODES) return;
    const float* row = cb + (size_t)k * DDIM;
    float s = 0.f;
    for (int d = 0; d < DDIM; d += 4) {
        float4 v = *(const float4*)&row[d];
        s = __fadd_rn(s, __fmul_rn(v.x, v.x));
        s = __fadd_rn(s, __fmul_rn(v.y, v.y));
        s = __fadd_rn(s, __fmul_rn(v.z, v.z));
        s = __fadd_rn(s, __fmul_rn(v.w, v.w));
    }
    g_esq[k] = s;
}

// ||z_n||^2 : serial mul-then-add, ascending d (no FMA contraction)
__global__ void zsq_kernel(const float* __restrict__ z) {
    int n = blockIdx.x * blockDim.x + threadIdx.x;
    if (n >= NROWS) return;
    const float* row = z + (size_t)n * DDIM;
    float s = 0.f;
    for (int d = 0; d < DDIM; d += 4) {
        float4 v = __ldg((const float4*)&row[d]);
        s = __fadd_rn(s, __fmul_rn(v.x, v.x));
        s = __fadd_rn(s, __fmul_rn(v.y, v.y));
        s = __fadd_rn(s, __fmul_rn(v.z, v.z));
        s = __fadd_rn(s, __fmul_rn(v.w, v.w));
    }
    g_zsq[n] = s;
}

__global__ __launch_bounds__(256, 2)
void vq_main_kernel(const float* __restrict__ z, const float* __restrict__ cb,
                    float* __restrict__ out) {
    __shared__ float zs[DCH][SSTR];   // z tile, transposed: [d][row]
    __shared__ float es[DCH][SSTR];   // codebook tile, transposed: [d][code]
    __shared__ int   sidx[BM];

    const int t  = threadIdx.x;
    const int tx = t & 15;            // code sub-tile (8 codes)
    const int ty = t >> 4;            // row sub-tile  (8 rows)
    const int rowbase = blockIdx.x * BM;
    const int q  = t & 7;             // 4-dim quad within DCH
    const int r0 = t >> 3;            // 0..31

    float minv[8];
    int   mini[8];
    float zsqr[8];
    #pragma unroll
    for (int i = 0; i < 8; i++) {
        minv[i] = 3.4e38f; mini[i] = 0;
        zsqr[i] = g_zsq[rowbase + ty * 8 + i];
    }

    for (int kc = 0; kc < KCODES; kc += BKC) {
        float acc[8][8];
        #pragma unroll
        for (int i = 0; i < 8; i++)
            #pragma unroll
            for (int j = 0; j < 8; j++) acc[i][j] = 0.f;

        // serial ascending-d accumulation (single accumulator per output)
        for (int d0 = 0; d0 < DDIM; d0 += DCH) {
            #pragma unroll
            for (int p = 0; p < 4; p++) {
                int row = r0 + 32 * p;
                float4 v = *(const float4*)&z[(size_t)(rowbase + row) * DDIM + d0 + 4 * q];
                zs[4*q+0][row] = v.x; zs[4*q+1][row] = v.y;
                zs[4*q+2][row] = v.z; zs[4*q+3][row] = v.w;
                float4 w = *(const float4*)&cb[(size_t)(kc + row) * DDIM + d0 + 4 * q];
                es[4*q+0][row] = w.x; es[4*q+1][row] = w.y;
                es[4*q+2][row] = w.z; es[4*q+3][row] = w.w;
            }
            __syncthreads();
            #pragma unroll 4
            for (int dk = 0; dk < DCH; dk++) {
                float4 a0 = *(const float4*)&zs[dk][ty * 8];
                float4 a1 = *(const float4*)&zs[dk][ty * 8 + 4];
                float4 b0 = *(const float4*)&es[dk][tx * 8];
                float4 b1 = *(const float4*)&es[dk][tx * 8 + 4];
                float a[8] = {a0.x, a0.y, a0.z, a0.w, a1.x, a1.y, a1.z, a1.w};
                float b[8] = {b0.x, b0.y, b0.z, b0.w, b1.x, b1.y, b1.z, b1.w};
                #pragma unroll
                for (int i = 0; i < 8; i++)
                    #pragma unroll
                    for (int j = 0; j < 8; j++)
                        acc[i][j] = fmaf(a[i], b[j], acc[i][j]);
            }
            __syncthreads();
        }
        // distances with EXACT reference op order:
        //   dist = fadd( fsub(z_sq, 2*cross), e_sq )
        #pragma unroll
        for (int j = 0; j < 8; j++) {
            int code = kc + tx * 8 + j;
            float eq = g_esq[code];
            #pragma unroll
            for (int i = 0; i < 8; i++) {
                float dist = __fadd_rn(__fsub_rn(zsqr[i], __fmul_rn(2.0f, acc[i][j])), eq);
                // strict < with ascending code order => first occurrence kept
                if (dist < minv[i]) { minv[i] = dist; mini[i] = code; }
            }
        }
    }

    // cross-thread (tx) argmin reduction per row, lowest-index tie-break
    float* redv = &zs[0][0];          // 128*16 floats = 8 KB
    int*   redi = (int*)&es[0][0];    // 128*16 ints   = 8 KB
    __syncthreads();
    #pragma unroll
    for (int i = 0; i < 8; i++) {
        int row = ty * 8 + i;
        redv[row * 16 + tx] = minv[i];
        redi[row * 16 + tx] = mini[i];
    }
    __syncthreads();
    if (t < BM) {
        float bv = redv[t * 16];
        int   bi = redi[t * 16];
        #pragma unroll
        for (int c = 1; c < 16; c++) {
            float v  = redv[t * 16 + c];
            int   ii = redi[t * 16 + c];
            if (v < bv || (v == bv && ii < bi)) { bv = v; bi = ii; }
        }
        sidx[t] = bi;
    }
    __syncthreads();

    // gather z_q, write out, accumulate commitment-loss partial
    float lsum = 0.f;
    for (int r = 0; r < BM; r++) {
        int idx = sidx[r];
        float zq = cb[(size_t)idx * DDIM + t];
        float ze = z[(size_t)(rowbase + r) * DDIM + t];
        out[(size_t)(rowbase + r) * DDIM + t] = zq;
        float df = zq - ze;
        lsum = fmaf(df, df, lsum);
    }
    __syncthreads();
    redv[t] = lsum;
    __syncthreads();
    for (int s = 128; s > 0; s >>= 1) {
        if (t < s) redv[t] += redv[t + s];
        __syncthreads();
    }
    if (t == 0) g_partial[blockIdx.x] = redv[0];
}

__global__ void finalize_kernel(float* __restrict__ out, int out_size) {
    __shared__ float s_loss;
    if (threadIdx.x == 0) {
        float s = 0.f;
        for (int i = 0; i < NBLOCKS; i++) s += g_partial[i];   // fixed order: deterministic
        s_loss = s / (float)((long long)NROWS * DDIM);
    }
    __syncthreads();
    const long long base = (long long)NROWS * DDIM;
    for (long long i = base + threadIdx.x; i < (long long)out_size; i += blockDim.x)
        out[i] = s_loss;
}

extern "C" void kernel_launch(void* const* d_in, const int* in_sizes, int n_in,
                              void* d_out, int out_size) {
    const float* z  = (const float*)d_in[0];
    const float* cb = (const float*)d_in[1];
    if (n_in >= 2 && in_sizes[0] == KCODES * DDIM && in_sizes[1] == NROWS * DDIM) {
        z  = (const float*)d_in[1];
        cb = (const float*)d_in[0];
    }
    float* out = (float*)d_out;

    esq_kernel<<<(KCODES + 255) / 256, 256>>>(cb);
    zsq_kernel<<<NROWS / 256, 256>>>(z);
    vq_main_kernel<<<NBLOCKS, 256>>>(z, cb, out);
    finalize_kernel<<<1, 256>>>(out, out_size);
}

// round 3
// speedup vs baseline: 1.0108x; 1.0108x over previous
#include <cuda_runtime.h>

// VQ-VAE quantization: z_e [65536, 256] f32, codebook [1024, 256] f32.
// Bit-replicates reference semantics (validated in R2):
//   z_sq  = serial mul-then-add (no FMA contraction)
//   cross = serial ascending-d single-accumulator FMA
//   dist  = fadd(fsub(z_sq, 2*cross), e_sq)
//   argmin with lowest-index tie-break
// R3: mainloop switched to packed fma.rn.f32x2 (FFMA2, full-rate fp32 on B300).
//     Each f32x2 lane is a bitwise-identical fp32 FMA in the same order.

#define NROWS   65536
#define DDIM    256
#define KCODES  1024
#define BM      128
#define BKC     128
#define DCH     32
#define SSTR    132
#define NBLOCKS (NROWS / BM)   // 512

typedef unsigned long long u64;

__device__ __forceinline__ u64 pk2(float lo, float hi) {
    u64 r; asm("mov.b64 %0, {%1, %2};" : "=l"(r) : "f"(lo), "f"(hi)); return r;
}
__device__ __forceinline__ void upk2(u64 v, float& lo, float& hi) {
    asm("mov.b64 {%0, %1}, %2;" : "=f"(lo), "=f"(hi) : "l"(v));
}
__device__ __forceinline__ void ffma2(u64& d, u64 a, u64 b) {
    asm("fma.rn.f32x2 %0, %1, %2, %0;" : "+l"(d) : "l"(a), "l"(b));
}

__device__ float g_esq[KCODES];
__device__ float g_zsq[NROWS];
__device__ float g_partial[NBLOCKS];

__global__ void esq_kernel(const float* __restrict__ cb) {
    int k = blockIdx.x * blockDim.x + threadIdx.x;
    if (k >= KCODES) return;
    const float* row = cb + (size_t)k * DDIM;
    float s = 0.f;
    for (int d = 0; d < DDIM; d += 4) {
        float4 v = *(const float4*)&row[d];
        s = __fadd_rn(s, __fmul_rn(v.x, v.x));
        s = __fadd_rn(s, __fmul_rn(v.y, v.y));
        s = __fadd_rn(s, __fmul_rn(v.z, v.z));
        s = __fadd_rn(s, __fmul_rn(v.w, v.w));
    }
    g_esq[k] = s;
}

__global__ void zsq_kernel(const float* __restrict__ z) {
    int n = blockIdx.x * blockDim.x + threadIdx.x;
    if (n >= NROWS) return;
    const float* row = z + (size_t)n * DDIM;
    float s = 0.f;
    for (int d = 0; d < DDIM; d += 4) {
        float4 v = __ldg((const float4*)&row[d]);
        s = __fadd_rn(s, __fmul_rn(v.x, v.x));
        s = __fadd_rn(s, __fmul_rn(v.y, v.y));
        s = __fadd_rn(s, __fmul_rn(v.z, v.z));
        s = __fadd_rn(s, __fmul_rn(v.w, v.w));
    }
    g_zsq[n] = s;
}

__global__ __launch_bounds__(256, 2)
void vq_main_kernel(const float* __restrict__ z, const float* __restrict__ cb,
                    float* __restrict__ out) {
    __shared__ float zs[DCH][SSTR];
    __shared__ float es[DCH][SSTR];
    __shared__ int   sidx[BM];

    const int t  = threadIdx.x;
    const int tx = t & 15;
    const int ty = t >> 4;
    const int rowbase = blockIdx.x * BM;
    const int q  = t & 7;
    const int r0 = t >> 3;

    float minv[8];
    int   mini[8];
    float zsqr[8];
    #pragma unroll
    for (int i = 0; i < 8; i++) {
        minv[i] = 3.4e38f; mini[i] = 0;
        zsqr[i] = g_zsq[rowbase + ty * 8 + i];
    }

    for (int kc = 0; kc < KCODES; kc += BKC) {
        u64 acc2[8][4];   // pairs along j: acc2[i][j2] = (acc[i][2j2], acc[i][2j2+1])
        u64 z2 = pk2(0.f, 0.f);
        #pragma unroll
        for (int i = 0; i < 8; i++)
            #pragma unroll
            for (int j = 0; j < 4; j++) acc2[i][j] = z2;

        for (int d0 = 0; d0 < DDIM; d0 += DCH) {
            #pragma unroll
            for (int p = 0; p < 4; p++) {
                int row = r0 + 32 * p;
                float4 v = *(const float4*)&z[(size_t)(rowbase + row) * DDIM + d0 + 4 * q];
                zs[4*q+0][row] = v.x; zs[4*q+1][row] = v.y;
                zs[4*q+2][row] = v.z; zs[4*q+3][row] = v.w;
                float4 w = *(const float4*)&cb[(size_t)(kc + row) * DDIM + d0 + 4 * q];
                es[4*q+0][row] = w.x; es[4*q+1][row] = w.y;
                es[4*q+2][row] = w.z; es[4*q+3][row] = w.w;
            }
            __syncthreads();
            #pragma unroll 4
            for (int dk = 0; dk < DCH; dk++) {
                float4 a0 = *(const float4*)&zs[dk][ty * 8];
                float4 a1 = *(const float4*)&zs[dk][ty * 8 + 4];
                float4 b0 = *(const float4*)&es[dk][tx * 8];
                float4 b1 = *(const float4*)&es[dk][tx * 8 + 4];
                u64 bb0 = pk2(b0.x, b0.y);
                u64 bb1 = pk2(b0.z, b0.w);
                u64 bb2 = pk2(b1.x, b1.y);
                u64 bb3 = pk2(b1.z, b1.w);
                float av[8] = {a0.x, a0.y, a0.z, a0.w, a1.x, a1.y, a1.z, a1.w};
                #pragma unroll
                for (int i = 0; i < 8; i++) {
                    u64 aa = pk2(av[i], av[i]);
                    ffma2(acc2[i][0], aa, bb0);
                    ffma2(acc2[i][1], aa, bb1);
                    ffma2(acc2[i][2], aa, bb2);
                    ffma2(acc2[i][3], aa, bb3);
                }
            }
            __syncthreads();
        }
        // distances: dist = fadd( fsub(z_sq, 2*cross), e_sq ), exact ref order
        #pragma unroll
        for (int j2 = 0; j2 < 4; j2++) {
            int code0 = kc + tx * 8 + 2 * j2;
            float eq0 = g_esq[code0];
            float eq1 = g_esq[code0 + 1];
            #pragma unroll
            for (int i = 0; i < 8; i++) {
                float c0, c1;
                upk2(acc2[i][j2], c0, c1);
                float d0_ = __fadd_rn(__fsub_rn(zsqr[i], __fmul_rn(2.0f, c0)), eq0);
                float d1_ = __fadd_rn(__fsub_rn(zsqr[i], __fmul_rn(2.0f, c1)), eq1);
                if (d0_ < minv[i]) { minv[i] = d0_; mini[i] = code0; }
                if (d1_ < minv[i]) { minv[i] = d1_; mini[i] = code0 + 1; }
            }
        }
    }

    // cross-thread (tx) argmin reduction per row, lowest-index tie-break
    float* redv = &zs[0][0];
    int*   redi = (int*)&es[0][0];
    __syncthreads();
    #pragma unroll
    for (int i = 0; i < 8; i++) {
        int row = ty * 8 + i;
        redv[row * 16 + tx] = minv[i];
        redi[row * 16 + tx] = mini[i];
    }
    __syncthreads();
    if (t < BM) {
        float bv = redv[t * 16];
        int   bi = redi[t * 16];
        #pragma unroll
        for (int c = 1; c < 16; c++) {
            float v  = redv[t * 16 + c];
            int   ii = redi[t * 16 + c];
            if (v < bv || (v == bv && ii < bi)) { bv = v; bi = ii; }
        }
        sidx[t] = bi;
    }
    __syncthreads();

    // gather z_q, write out, accumulate commitment-loss partial
    float lsum = 0.f;
    for (int r = 0; r < BM; r++) {
        int idx = sidx[r];
        float zq = cb[(size_t)idx * DDIM + t];
        float ze = z[(size_t)(rowbase + r) * DDIM + t];
        out[(size_t)(rowbase + r) * DDIM + t] = zq;
        float df = zq - ze;
        lsum = fmaf(df, df, lsum);
    }
    __syncthreads();
    redv[t] = lsum;
    __syncthreads();
    for (int s = 128; s > 0; s >>= 1) {
        if (t < s) redv[t] += redv[t + s];
        __syncthreads();
    }
    if (t == 0) g_partial[blockIdx.x] = redv[0];
}

__global__ void finalize_kernel(float* __restrict__ out, int out_size) {
    __shared__ float red[512];
    int t = threadIdx.x;
    red[t] = g_partial[t];                 // 512 threads, fixed deterministic tree
    __syncthreads();
    for (int s = 256; s > 0; s >>= 1) {
        if (t < s) red[t] += red[t + s];
        __syncthreads();
    }
    float loss = red[0] / (float)((long long)NROWS * DDIM);
    const long long base = (long long)NROWS * DDIM;
    for (long long i = base + t; i < (long long)out_size; i += blockDim.x)
        out[i] = loss;
}

extern "C" void kernel_launch(void* const* d_in, const int* in_sizes, int n_in,
                              void* d_out, int out_size) {
    const float* z  = (const float*)d_in[0];
    const float* cb = (const float*)d_in[1];
    if (n_in >= 2 && in_sizes[0] == KCODES * DDIM && in_sizes[1] == NROWS * DDIM) {
        z  = (const float*)d_in[1];
        cb = (const float*)d_in[0];
    }
    float* out = (float*)d_out;

    esq_kernel<<<(KCODES + 255) / 256, 256>>>(cb);
    zsq_kernel<<<NROWS / 256, 256>>>(z);
    vq_main_kernel<<<NBLOCKS, 256>>>(z, cb, out);
    finalize_kernel<<<1, 512>>>(out, out_size);
}